// round 11
// baseline (speedup 1.0000x reference)
#include <cuda_runtime.h>
#include <cuda_fp16.h>

#define C 128
#define NUM_ITERS 10
#define PGRID 592          // 4 blocks/SM * 148 SMs co-resident
#define PBLK  256
#define NWARPS_BLK (PBLK / 32)
#define STAGES 4
#define CROWS 9            // cached row-groups (512 B each) per warp
#define PIPE_BYTES (STAGES * 512)
#define CACHE_BYTES (CROWS * 512)
#define DSMEM (NWARPS_BLK * (PIPE_BYTES + CACHE_BYTES))   // 53248 B
#define CONV_TOL 1e-4f
#define MAXN 500000

// Scratch (__device__ globals, no allocation).
__device__ float g_b[C];
__device__ float g_colsum[NUM_ITERS + 1][C];
__device__ int   g_arrive;
__device__ int   g_gen;
__device__ uint4 g_E8[(size_t)MAXN * 8];         // E = exp(S) fp8 e4m3, 128 B/row

// ---- fp8 helpers ------------------------------------------------------------
__device__ __forceinline__ unsigned short pack_fp8x2(float hi, float lo) {
    unsigned short v;
    asm("cvt.rn.satfinite.e4m3x2.f32 %0, %1, %2;" : "=h"(v) : "f"(hi), "f"(lo));
    return v;
}
__device__ __forceinline__ __half2 fp8x2_to_h2(unsigned short p) {
    unsigned r;
    asm("cvt.rn.f16x2.e4m3x2 %0, %1;" : "=r"(r) : "h"(p));
    return *reinterpret_cast<__half2*>(&r);
}

// ---- cache-policy helpers ---------------------------------------------------
__device__ __forceinline__ unsigned long long pol_evict_last() {
    unsigned long long p;
    asm("createpolicy.fractional.L2::evict_last.b64 %0, 1.0;" : "=l"(p));
    return p;
}
__device__ __forceinline__ unsigned long long pol_evict_first() {
    unsigned long long p;
    asm("createpolicy.fractional.L2::evict_first.b64 %0, 1.0;" : "=l"(p));
    return p;
}
__device__ __forceinline__ void stg_hint_u32(unsigned* p, unsigned v, unsigned long long pol) {
    asm volatile("st.global.L2::cache_hint.u32 [%0], %1, %2;"
                 :: "l"(p), "r"(v), "l"(pol) : "memory");
}
__device__ __forceinline__ void stg_hint_f4(float4* p, float4 v, unsigned long long pol) {
    asm volatile("st.global.L2::cache_hint.v4.f32 [%0], {%1,%2,%3,%4}, %5;"
                 :: "l"(p), "f"(v.x), "f"(v.y), "f"(v.z), "f"(v.w), "l"(pol) : "memory");
}

// ---- cp.async / shared helpers ----------------------------------------------
__device__ __forceinline__ void cp_async16(unsigned dst, const void* src) {
    asm volatile("cp.async.cg.shared.global [%0], [%1], 16;" :: "r"(dst), "l"(src) : "memory");
}
#define CP_COMMIT() asm volatile("cp.async.commit_group;" ::: "memory")
#define CP_WAIT(n)  asm volatile("cp.async.wait_group %0;" :: "n"(n) : "memory")
__device__ __forceinline__ uint4 lds128(unsigned addr) {
    uint4 q;
    asm volatile("ld.shared.v4.u32 {%0,%1,%2,%3}, [%4];"
                 : "=r"(q.x), "=r"(q.y), "=r"(q.z), "=r"(q.w) : "r"(addr));
    return q;
}
__device__ __forceinline__ void sts32(unsigned addr, unsigned v) {
    asm volatile("st.shared.u32 [%0], %1;" :: "r"(addr), "r"(v) : "memory");
}

// ---------------------------------------------------------------------------
__global__ void init_k(const float* __restrict__ ratios,
                       const int* __restrict__ total_num) {
    int j = threadIdx.x;
    float tn = (float)(*total_num);
    g_b[j] = ratios[j] * tn;
    #pragma unroll
    for (int t = 0; t <= NUM_ITERS; ++t) g_colsum[t][j] = 0.0f;
    if (j == 0) { g_arrive = 0; g_gen = 0; }
}

// ---------------------------------------------------------------------------
__device__ __forceinline__ void grid_barrier(int gen) {
    __threadfence();
    __syncthreads();
    if (threadIdx.x == 0) {
        int prev = atomicAdd(&g_arrive, 1);
        if (prev == gen * PGRID - 1) {
            atomicExch(&g_gen, gen);
        } else {
            int cur;
            do {
                asm volatile("ld.global.cg.s32 %0, [%1];" : "=r"(cur) : "l"(&g_gen));
                if (cur < gen) __nanosleep(32);
            } while (cur < gen);
        }
        __threadfence();
    }
    __syncthreads();
}

// ---------------------------------------------------------------------------
// Grand persistent kernel. Group-major row order everywhere: warp owns
// row-groups m = gwarp + k*nwarps (4 rows each); first KC groups of each warp
// are mirrored into SMEM during Phase A and read from SMEM in Phase B.
// ---------------------------------------------------------------------------
__global__ void __launch_bounds__(PBLK, 4)
grand_k(const float* __restrict__ S, float* __restrict__ out, int N) {
    const int lane = threadIdx.x & 31;
    const int sub = lane & 7;
    const int wid = threadIdx.x >> 5;
    const int gwarp = blockIdx.x * NWARPS_BLK + wid;
    const int nwarps = PGRID * NWARPS_BLK;
    const int G = N >> 2;
    const int remN = N & 3;
    const unsigned long long pol_el = pol_evict_last();
    const unsigned long long pol_ef = pol_evict_first();

    __shared__ float sv[C];
    __shared__ float svB[C];
    __shared__ float scol[C];
    extern __shared__ __align__(16) unsigned char dyn[];

    const unsigned dbase = (unsigned)__cvta_generic_to_shared(dyn);
    const unsigned pbuf = dbase + (unsigned)wid * PIPE_BYTES + (unsigned)lane * 16;
    const unsigned cbase = dbase + NWARPS_BLK * PIPE_BYTES + (unsigned)wid * CACHE_BYTES;

    const int ngrp = (gwarp < G) ? ((G - gwarp - 1) / nwarps + 1) : 0;
    const int KC = (ngrp < CROWS) ? ngrp : CROWS;
    const int nrowsA = 4 * ngrp;               // group-phase rows in Phase A

    // row id for Phase-A step k: 4*(gwarp + (k>>2)*nwarps) + (k&3)
    auto rowA = [&](int k) -> size_t {
        return (size_t)4 * gwarp + (size_t)(k >> 2) * (4 * nwarps) + (k & 3);
    };

    // ======================= Phase A: iteration 1 + E8 store ================
    {
        if (threadIdx.x < C) scol[threadIdx.x] = 0.0f;
        __syncthreads();

        float c0 = 0.f, c1 = 0.f, c2 = 0.f, c3 = 0.f;
        unsigned* __restrict__ E8 = reinterpret_cast<unsigned*>(g_E8);

        int j = 0;
        #pragma unroll
        for (int s = 0; s < STAGES; ++s) {
            if (j < nrowsA)
                cp_async16(pbuf + s * 512, S + rowA(j) * C + lane * 4);
            CP_COMMIT();
            ++j;
        }
        for (int k = 0; k < nrowsA; ++k) {
            CP_WAIT(STAGES - 1);
            uint4 q = lds128(pbuf + (k & (STAGES - 1)) * 512);
            size_t row = rowA(k);
            float e0 = __expf(__uint_as_float(q.x));
            float e1 = __expf(__uint_as_float(q.y));
            float e2 = __expf(__uint_as_float(q.z));
            float e3 = __expf(__uint_as_float(q.w));
            unsigned pk = (unsigned)pack_fp8x2(e1, e0)
                        | ((unsigned)pack_fp8x2(e3, e2) << 16);
            int grp = k >> 2;
            if (grp < KC) {
                sts32(cbase + grp * 512 + (k & 3) * 128 + lane * 4, pk);
            } else {
                stg_hint_u32(&E8[row * 32 + lane], pk, pol_el);
            }
            float p = (e0 + e1) + (e2 + e3);
            #pragma unroll
            for (int o = 16; o; o >>= 1) p += __shfl_xor_sync(0xffffffffu, p, o);
            float u = 1.0f / p;
            c0 = fmaf(u, e0, c0); c1 = fmaf(u, e1, c1);
            c2 = fmaf(u, e2, c2); c3 = fmaf(u, e3, c3);
            if (j < nrowsA)
                cp_async16(pbuf + (j & (STAGES - 1)) * 512, S + rowA(j) * C + lane * 4);
            CP_COMMIT();
            ++j;
        }
        CP_WAIT(0);

        // Tail rows (N % 4) — streamed, stored to global (B's rem path reads global).
        for (int r = 4 * G + gwarp; r < N; r += nwarps) {
            float4 s4 = __ldg(reinterpret_cast<const float4*>(S + (size_t)r * C) + lane);
            float e0 = __expf(s4.x), e1 = __expf(s4.y), e2 = __expf(s4.z), e3 = __expf(s4.w);
            unsigned pk = (unsigned)pack_fp8x2(e1, e0) | ((unsigned)pack_fp8x2(e3, e2) << 16);
            stg_hint_u32(&E8[(size_t)r * 32 + lane], pk, pol_el);
            float p = (e0 + e1) + (e2 + e3);
            #pragma unroll
            for (int o = 16; o; o >>= 1) p += __shfl_xor_sync(0xffffffffu, p, o);
            float u = 1.0f / p;
            c0 = fmaf(u, e0, c0); c1 = fmaf(u, e1, c1);
            c2 = fmaf(u, e2, c2); c3 = fmaf(u, e3, c3);
        }

        int col = lane * 4;
        atomicAdd(&scol[col + 0], c0);
        atomicAdd(&scol[col + 1], c1);
        atomicAdd(&scol[col + 2], c2);
        atomicAdd(&scol[col + 3], c3);
        __syncthreads();
        if (threadIdx.x < C)
            atomicAdd(&g_colsum[1][threadIdx.x], scol[threadIdx.x]);
    }
    grid_barrier(1);

    // ======================= Phase B: iterations 2..10 ======================
    int tA = NUM_ITERS - 1, tB = NUM_ITERS;
    for (int t = 2; t <= NUM_ITERS; ++t) {
        int bigflag = 0;
        if (threadIdx.x < C) {
            float vn = g_b[threadIdx.x] / __ldcg(&g_colsum[t - 1][threadIdx.x]);
            sv[threadIdx.x] = vn;
            scol[threadIdx.x] = 0.0f;
            if (t >= 3) {
                float vo = g_b[threadIdx.x] / __ldcg(&g_colsum[t - 2][threadIdx.x]);
                bigflag = fabsf(vn - vo) > CONV_TOL * vn;
            }
        }
        int moving = __syncthreads_or(bigflag);
        if (t >= 3 && !moving) {      // identical decision in every block
            tA = t - 1; tB = t - 1;
            break;
        }

        __half2 v2[8], c2[8];
        #pragma unroll
        for (int k = 0; k < 8; ++k) {
            v2[k] = __floats2half2_rn(sv[sub * 16 + 2 * k], sv[sub * 16 + 2 * k + 1]);
            c2[k] = __floats2half2_rn(0.f, 0.f);
        }

        auto process = [&](uint4 q) {
            __half2 h[8];
            h[0] = fp8x2_to_h2((unsigned short)(q.x & 0xffff));
            h[1] = fp8x2_to_h2((unsigned short)(q.x >> 16));
            h[2] = fp8x2_to_h2((unsigned short)(q.y & 0xffff));
            h[3] = fp8x2_to_h2((unsigned short)(q.y >> 16));
            h[4] = fp8x2_to_h2((unsigned short)(q.z & 0xffff));
            h[5] = fp8x2_to_h2((unsigned short)(q.z >> 16));
            h[6] = fp8x2_to_h2((unsigned short)(q.w & 0xffff));
            h[7] = fp8x2_to_h2((unsigned short)(q.w >> 16));
            __half2 pa = __hmul2(h[0], v2[0]);
            __half2 pb = __hmul2(h[4], v2[4]);
            pa = __hfma2(h[1], v2[1], pa);
            pb = __hfma2(h[5], v2[5], pb);
            pa = __hfma2(h[2], v2[2], pa);
            pb = __hfma2(h[6], v2[6], pb);
            pa = __hfma2(h[3], v2[3], pa);
            pb = __hfma2(h[7], v2[7], pb);
            pa = __hadd2(pa, pb);
            float2 pf = __half22float2(pa);
            float p = pf.x + pf.y;
            p += __shfl_xor_sync(0xffffffffu, p, 4);
            p += __shfl_xor_sync(0xffffffffu, p, 2);
            p += __shfl_xor_sync(0xffffffffu, p, 1);
            __half2 u2 = __float2half2_rn(1.0f / p);
            #pragma unroll
            for (int k = 0; k < 8; ++k)
                c2[k] = __hfma2(u2, h[k], c2[k]);
        };

        // Streamed pipeline over groups k in [KC, ngrp); cached k in [0, KC)
        // interleaved 2:1 so LTS streaming never idles.
        int j = KC;
        #pragma unroll
        for (int s = 0; s < STAGES; ++s) {
            if (j < ngrp)
                cp_async16(pbuf + s * 512,
                           &g_E8[((size_t)gwarp + (size_t)j * nwarps) * 32 + lane]);
            CP_COMMIT();
            ++j;
        }
        int cs = KC, cc = 0;
        while (cs < ngrp || cc < KC) {
            #pragma unroll
            for (int r = 0; r < 2; ++r) {
                if (cs < ngrp) {
                    CP_WAIT(STAGES - 1);
                    uint4 q = lds128(pbuf + ((cs - KC) & (STAGES - 1)) * 512);
                    process(q);
                    if (j < ngrp)
                        cp_async16(pbuf + ((j - KC) & (STAGES - 1)) * 512,
                                   &g_E8[((size_t)gwarp + (size_t)j * nwarps) * 32 + lane]);
                    CP_COMMIT();
                    ++j;
                    ++cs;
                }
            }
            if (cc < KC) {
                uint4 q = lds128(cbase + cc * 512 + lane * 16);
                process(q);
                ++cc;
            }
        }
        CP_WAIT(0);

        if (gwarp < remN && lane < 8) {   // remainder rows (N % 4)
            size_t row = (size_t)G * 4 + gwarp;
            uint4 q = g_E8[row * 8 + sub];
            __half2 h[8];
            h[0] = fp8x2_to_h2((unsigned short)(q.x & 0xffff));
            h[1] = fp8x2_to_h2((unsigned short)(q.x >> 16));
            h[2] = fp8x2_to_h2((unsigned short)(q.y & 0xffff));
            h[3] = fp8x2_to_h2((unsigned short)(q.y >> 16));
            h[4] = fp8x2_to_h2((unsigned short)(q.z & 0xffff));
            h[5] = fp8x2_to_h2((unsigned short)(q.z >> 16));
            h[6] = fp8x2_to_h2((unsigned short)(q.w & 0xffff));
            h[7] = fp8x2_to_h2((unsigned short)(q.w >> 16));
            float p = 0.f;
            #pragma unroll
            for (int k = 0; k < 8; ++k) {
                float2 pr = __half22float2(__hmul2(h[k], v2[k]));
                p += pr.x + pr.y;
            }
            p += __shfl_xor_sync(0x000000ffu, p, 4);
            p += __shfl_xor_sync(0x000000ffu, p, 2);
            p += __shfl_xor_sync(0x000000ffu, p, 1);
            __half2 u2 = __float2half2_rn(1.0f / p);
            #pragma unroll
            for (int k = 0; k < 8; ++k)
                c2[k] = __hfma2(u2, h[k], c2[k]);
        }

        #pragma unroll
        for (int k = 0; k < 8; ++k) {
            unsigned pk = *reinterpret_cast<unsigned*>(&c2[k]);
            unsigned o1 = __shfl_xor_sync(0xffffffffu, pk, 8);
            __half2 s = __hadd2(c2[k], *reinterpret_cast<__half2*>(&o1));
            unsigned ps = *reinterpret_cast<unsigned*>(&s);
            unsigned o2 = __shfl_xor_sync(0xffffffffu, ps, 16);
            c2[k] = __hadd2(s, *reinterpret_cast<__half2*>(&o2));
        }
        if (lane < 8) {
            #pragma unroll
            for (int k = 0; k < 8; ++k) {
                float2 cf = __half22float2(c2[k]);
                atomicAdd(&scol[sub * 16 + 2 * k], cf.x);
                atomicAdd(&scol[sub * 16 + 2 * k + 1], cf.y);
            }
        }
        __syncthreads();
        if (threadIdx.x < C)
            atomicAdd(&g_colsum[t][threadIdx.x], scol[threadIdx.x]);

        grid_barrier(t);
    }

    // ======================= Phase C: final output ==========================
    {
        if (threadIdx.x < C) {
            sv[threadIdx.x]  = g_b[threadIdx.x] / __ldcg(&g_colsum[tA][threadIdx.x]);
            svB[threadIdx.x] = g_b[threadIdx.x] / __ldcg(&g_colsum[tB][threadIdx.x]);
        }
        __syncthreads();

        float4 va = reinterpret_cast<const float4*>(sv)[lane];
        float4 vb = reinterpret_cast<const float4*>(svB)[lane];
        float4* __restrict__ out4 = reinterpret_cast<float4*>(out);

        const int nrows = (gwarp < N) ? ((N - gwarp - 1) / nwarps + 1) : 0;
        int j = 0;
        #pragma unroll
        for (int s = 0; s < STAGES; ++s) {
            if (j < nrows)
                cp_async16(pbuf + s * 512,
                           S + ((size_t)gwarp + (size_t)j * nwarps) * C + lane * 4);
            CP_COMMIT();
            ++j;
        }
        for (int k = 0; k < nrows; ++k) {
            CP_WAIT(STAGES - 1);
            uint4 q = lds128(pbuf + (k & (STAGES - 1)) * 512);
            size_t row = (size_t)gwarp + (size_t)k * nwarps;
            float e0 = __expf(__uint_as_float(q.x));
            float e1 = __expf(__uint_as_float(q.y));
            float e2 = __expf(__uint_as_float(q.z));
            float e3 = __expf(__uint_as_float(q.w));
            float p = fmaf(e0, va.x, fmaf(e1, va.y, fmaf(e2, va.z, e3 * va.w)));
            #pragma unroll
            for (int o = 16; o; o >>= 1) p += __shfl_xor_sync(0xffffffffu, p, o);
            float u = 1.0f / p;
            float4 o4;
            o4.x = u * e0 * vb.x; o4.y = u * e1 * vb.y;
            o4.z = u * e2 * vb.z; o4.w = u * e3 * vb.w;
            stg_hint_f4(&out4[row * 32 + lane], o4, pol_ef);
            if (j < nrows)
                cp_async16(pbuf + (j & (STAGES - 1)) * 512,
                           S + ((size_t)gwarp + (size_t)j * nwarps) * C + lane * 4);
            CP_COMMIT();
            ++j;
        }
        CP_WAIT(0);
    }
}

// ---------------------------------------------------------------------------
extern "C" void kernel_launch(void* const* d_in, const int* in_sizes, int n_in,
                              void* d_out, int out_size) {
    const float* S        = (const float*)d_in[2];
    const float* ratios   = (const float*)d_in[3];
    const int*   totalnum = (const int*)d_in[5];
    const int N = in_sizes[2] / C;

    cudaFuncSetAttribute(grand_k, cudaFuncAttributeMaxDynamicSharedMemorySize, DSMEM);

    init_k<<<1, C>>>(ratios, totalnum);
    grand_k<<<PGRID, PBLK, DSMEM>>>(S, (float*)d_out, N);
}